// round 1
// baseline (speedup 1.0000x reference)
#include <cuda_runtime.h>

#define BB   8
#define CC   128
#define WHQ  2304
#define NN   8192

#define TQ   64
#define TN   64
#define KSTR 132   // K tile row stride (floats): 128+4, float4-aligned, 2-way max conflict
#define SSTR 68    // S tile row stride (floats): 64+4, float4-aligned

// Scratch (device globals: allocation-free rule)
__device__ float g_pk  [BB*NN*CC];
__device__ float g_pv  [BB*NN*CC];
__device__ float g_pq  [BB*WHQ*CC];
__device__ float g_geo [BB*WHQ*CC];
__device__ float g_attn[BB*WHQ*CC];

// ---------------------------------------------------------------------------
// K1: pk = feat1^T @ Wk + bk ; pv = feat1^T @ Wv + bv
// feat1 layout [b, c, n] (n contiguous). Output [b, n, c].
// ---------------------------------------------------------------------------
__global__ __launch_bounds__(256) void kv_proj_kernel(
    const float* __restrict__ feat1,
    const float* __restrict__ Wk, const float* __restrict__ bk,
    const float* __restrict__ Wv, const float* __restrict__ bv)
{
    __shared__ float s_in[32][CC + 1];
    const int b  = blockIdx.y;
    const int n0 = blockIdx.x * 32;
    const int tid = threadIdx.x;
    const int tx = tid & 31;       // n within tile
    const int ty = tid >> 5;       // 0..7 -> group of 16 couts

    #pragma unroll
    for (int c = ty; c < CC; c += 8)
        s_in[tx][c] = feat1[(b*CC + c)*NN + n0 + tx];
    __syncthreads();

    float accK[16], accV[16];
    #pragma unroll
    for (int j = 0; j < 16; j++) { accK[j] = bk[ty*16 + j]; accV[j] = bv[ty*16 + j]; }

    #pragma unroll 4
    for (int c = 0; c < CC; c++) {
        const float a = s_in[tx][c];
        const float4* wk4 = reinterpret_cast<const float4*>(&Wk[c*CC + ty*16]);
        const float4* wv4 = reinterpret_cast<const float4*>(&Wv[c*CC + ty*16]);
        #pragma unroll
        for (int j4 = 0; j4 < 4; j4++) {
            float4 k4 = wk4[j4];
            float4 v4 = wv4[j4];
            accK[j4*4+0] = fmaf(a, k4.x, accK[j4*4+0]);
            accK[j4*4+1] = fmaf(a, k4.y, accK[j4*4+1]);
            accK[j4*4+2] = fmaf(a, k4.z, accK[j4*4+2]);
            accK[j4*4+3] = fmaf(a, k4.w, accK[j4*4+3]);
            accV[j4*4+0] = fmaf(a, v4.x, accV[j4*4+0]);
            accV[j4*4+1] = fmaf(a, v4.y, accV[j4*4+1]);
            accV[j4*4+2] = fmaf(a, v4.z, accV[j4*4+2]);
            accV[j4*4+3] = fmaf(a, v4.w, accV[j4*4+3]);
        }
    }

    const int base = (b*NN + n0 + tx)*CC + ty*16;
    #pragma unroll
    for (int j4 = 0; j4 < 4; j4++) {
        *reinterpret_cast<float4*>(&g_pk[base + j4*4]) =
            make_float4(accK[j4*4+0], accK[j4*4+1], accK[j4*4+2], accK[j4*4+3]);
        *reinterpret_cast<float4*>(&g_pv[base + j4*4]) =
            make_float4(accV[j4*4+0], accV[j4*4+1], accV[j4*4+2], accV[j4*4+3]);
    }
}

// ---------------------------------------------------------------------------
// K2: pq_raw = feat0^T @ Wq + bq ; geo = geo_embed @ Wg + bg
//     gate = sigmoid(pq_raw . Wgate[0:C] + geo . Wgate[C:2C] + bgate)
//     pq = pq_raw + gate * geo    (stores pq and geo)
// ---------------------------------------------------------------------------
__global__ __launch_bounds__(256) void q_geo_kernel(
    const float* __restrict__ feat0, const float* __restrict__ geo_embed,
    const float* __restrict__ Wq, const float* __restrict__ bq,
    const float* __restrict__ Wg, const float* __restrict__ bg,
    const float* __restrict__ Wgate, const float* __restrict__ bgate)
{
    __shared__ float s_q[32][CC + 1];
    __shared__ float s_g[32][CC + 1];
    __shared__ float s_part[8][32];
    __shared__ float s_gate[32];

    const int b  = blockIdx.y;
    const int q0 = blockIdx.x * 32;
    const int tid = threadIdx.x;
    const int tx = tid & 31;       // q within tile
    const int ty = tid >> 5;       // cout group

    #pragma unroll
    for (int c = ty; c < CC; c += 8)
        s_q[tx][c] = feat0[(b*CC + c)*WHQ + q0 + tx];
    #pragma unroll
    for (int i = tid; i < 32*CC; i += 256) {
        int q = i >> 7, c = i & 127;
        s_g[q][c] = geo_embed[(b*WHQ + q0 + q)*CC + c];
    }
    __syncthreads();

    float aq[16], ag[16];
    #pragma unroll
    for (int j = 0; j < 16; j++) { aq[j] = bq[ty*16 + j]; ag[j] = bg[ty*16 + j]; }

    #pragma unroll 4
    for (int c = 0; c < CC; c++) {
        const float xq = s_q[tx][c];
        const float xg = s_g[tx][c];
        const float4* wq4 = reinterpret_cast<const float4*>(&Wq[c*CC + ty*16]);
        const float4* wg4 = reinterpret_cast<const float4*>(&Wg[c*CC + ty*16]);
        #pragma unroll
        for (int j4 = 0; j4 < 4; j4++) {
            float4 q4 = wq4[j4];
            float4 g4 = wg4[j4];
            aq[j4*4+0] = fmaf(xq, q4.x, aq[j4*4+0]);
            aq[j4*4+1] = fmaf(xq, q4.y, aq[j4*4+1]);
            aq[j4*4+2] = fmaf(xq, q4.z, aq[j4*4+2]);
            aq[j4*4+3] = fmaf(xq, q4.w, aq[j4*4+3]);
            ag[j4*4+0] = fmaf(xg, g4.x, ag[j4*4+0]);
            ag[j4*4+1] = fmaf(xg, g4.y, ag[j4*4+1]);
            ag[j4*4+2] = fmaf(xg, g4.z, ag[j4*4+2]);
            ag[j4*4+3] = fmaf(xg, g4.w, ag[j4*4+3]);
        }
    }

    // gate reduction across the 8 cout groups
    float part = 0.f;
    #pragma unroll
    for (int j = 0; j < 16; j++)
        part += aq[j]*Wgate[ty*16 + j] + ag[j]*Wgate[CC + ty*16 + j];
    s_part[ty][tx] = part;
    __syncthreads();
    if (ty == 0) {
        float s = bgate[0];
        #pragma unroll
        for (int k = 0; k < 8; k++) s += s_part[k][tx];
        s_gate[tx] = 1.f / (1.f + __expf(-s));
    }
    __syncthreads();
    const float gate = s_gate[tx];

    const int base = (b*WHQ + q0 + tx)*CC + ty*16;
    #pragma unroll
    for (int j4 = 0; j4 < 4; j4++) {
        *reinterpret_cast<float4*>(&g_pq[base + j4*4]) =
            make_float4(aq[j4*4+0] + gate*ag[j4*4+0],
                        aq[j4*4+1] + gate*ag[j4*4+1],
                        aq[j4*4+2] + gate*ag[j4*4+2],
                        aq[j4*4+3] + gate*ag[j4*4+3]);
        *reinterpret_cast<float4*>(&g_geo[base + j4*4]) =
            make_float4(ag[j4*4+0], ag[j4*4+1], ag[j4*4+2], ag[j4*4+3]);
    }
}

// ---------------------------------------------------------------------------
// K3: flash-style attention. attn_out = (softmax(pq @ pk^T)/sqrt(C)) @ pv
// Block: 64 queries x full N loop, Tn=64. 256 threads.
// ---------------------------------------------------------------------------
#define ATTN_SMEM_FLOATS (TQ*CC + TN*KSTR + TN*CC + TQ*SSTR + 3*TQ)
#define ATTN_SMEM_BYTES  (ATTN_SMEM_FLOATS * 4)

__global__ __launch_bounds__(256) void attn_kernel()
{
    extern __shared__ float sm[];
    float* s_Q  = sm;                   // TQ*CC   (stride 128)
    float* s_K  = s_Q + TQ*CC;          // TN*KSTR (stride 132)
    float* s_V  = s_K + TN*KSTR;        // TN*CC   (stride 128)
    float* s_S  = s_V + TN*CC;          // TQ*SSTR (stride 68)
    float* s_m  = s_S + TQ*SSTR;        // TQ
    float* s_l  = s_m + TQ;             // TQ
    float* s_al = s_l + TQ;             // TQ

    const int b  = blockIdx.y;
    const int q0 = blockIdx.x * TQ;
    const int tid = threadIdx.x;
    const int txs = tid & 15;           // QK: n-col lane (cols txs + 16j)
    const int tys = tid >> 4;           // QK/PV: q-row group (rows tys*4..+4)

    // load Q tile
    {
        const float4* src = reinterpret_cast<const float4*>(&g_pq[(b*WHQ + q0)*CC]);
        float4* dst = reinterpret_cast<float4*>(s_Q);
        #pragma unroll
        for (int i = tid; i < TQ*CC/4; i += 256) dst[i] = src[i];
    }
    if (tid < TQ) { s_m[tid] = -1e30f; s_l[tid] = 0.f; }

    float acc[4][8];
    #pragma unroll
    for (int i = 0; i < 4; i++)
        #pragma unroll
        for (int k = 0; k < 8; k++) acc[i][k] = 0.f;

    const float4* gk4 = reinterpret_cast<const float4*>(&g_pk[b*NN*CC]);
    const float4* gv4 = reinterpret_cast<const float4*>(&g_pv[b*NN*CC]);

    for (int t = 0; t < NN/TN; ++t) {
        // ---- load K, V tiles ----
        const int base4 = t * TN * CC / 4;
        #pragma unroll
        for (int i = tid; i < TN*CC/4; i += 256) {
            int n = i >> 5, c4 = i & 31;
            float4 kv = gk4[base4 + i];
            *reinterpret_cast<float4*>(&s_K[n*KSTR + c4*4]) = kv;
            float4 vv = gv4[base4 + i];
            *reinterpret_cast<float4*>(&s_V[n*CC + c4*4]) = vv;
        }
        __syncthreads();

        // ---- S = Q @ K^T ----
        float s[4][4];
        #pragma unroll
        for (int i = 0; i < 4; i++)
            #pragma unroll
            for (int j = 0; j < 4; j++) s[i][j] = 0.f;

        #pragma unroll 2
        for (int c = 0; c < CC; c += 4) {
            float4 a4[4], b4[4];
            #pragma unroll
            for (int i = 0; i < 4; i++)
                a4[i] = *reinterpret_cast<const float4*>(&s_Q[(tys*4 + i)*CC + c]);
            #pragma unroll
            for (int j = 0; j < 4; j++)
                b4[j] = *reinterpret_cast<const float4*>(&s_K[(txs + 16*j)*KSTR + c]);
            #pragma unroll
            for (int i = 0; i < 4; i++)
                #pragma unroll
                for (int j = 0; j < 4; j++) {
                    s[i][j] = fmaf(a4[i].x, b4[j].x, s[i][j]);
                    s[i][j] = fmaf(a4[i].y, b4[j].y, s[i][j]);
                    s[i][j] = fmaf(a4[i].z, b4[j].z, s[i][j]);
                    s[i][j] = fmaf(a4[i].w, b4[j].w, s[i][j]);
                }
        }
        #pragma unroll
        for (int i = 0; i < 4; i++)
            #pragma unroll
            for (int j = 0; j < 4; j++)
                s_S[(tys*4 + i)*SSTR + txs + 16*j] = s[i][j];
        __syncthreads();

        // ---- online softmax (4 threads per row) ----
        {
            const int r = tid >> 2, sub = tid & 3;
            float mloc = -1e30f;
            #pragma unroll
            for (int k = 0; k < 16; k++)
                mloc = fmaxf(mloc, s_S[r*SSTR + sub + 4*k]);
            mloc = fmaxf(mloc, __shfl_xor_sync(0xffffffffu, mloc, 1));
            mloc = fmaxf(mloc, __shfl_xor_sync(0xffffffffu, mloc, 2));
            const float mold = s_m[r];
            const float mnew = fmaxf(mold, mloc);
            float sum = 0.f;
            #pragma unroll
            for (int k = 0; k < 16; k++) {
                float p = __expf(s_S[r*SSTR + sub + 4*k] - mnew);
                s_S[r*SSTR + sub + 4*k] = p;
                sum += p;
            }
            sum += __shfl_xor_sync(0xffffffffu, sum, 1);
            sum += __shfl_xor_sync(0xffffffffu, sum, 2);
            if (sub == 0) {
                const float alpha = __expf(mold - mnew);
                s_m[r]  = mnew;
                s_l[r]  = s_l[r]*alpha + sum;
                s_al[r] = alpha;
            }
        }
        __syncthreads();

        // ---- rescale acc, acc += P @ V ----
        {
            float al[4];
            #pragma unroll
            for (int i = 0; i < 4; i++) al[i] = s_al[tys*4 + i];
            #pragma unroll
            for (int i = 0; i < 4; i++)
                #pragma unroll
                for (int k = 0; k < 8; k++) acc[i][k] *= al[i];

            #pragma unroll 2
            for (int kk = 0; kk < TN; kk += 4) {
                float4 p4[4];
                #pragma unroll
                for (int i = 0; i < 4; i++)
                    p4[i] = *reinterpret_cast<const float4*>(&s_S[(tys*4 + i)*SSTR + kk]);
                #pragma unroll
                for (int u = 0; u < 4; u++) {
                    const float4 va = *reinterpret_cast<const float4*>(&s_V[(kk+u)*CC + txs*4]);
                    const float4 vb = *reinterpret_cast<const float4*>(&s_V[(kk+u)*CC + 64 + txs*4]);
                    #pragma unroll
                    for (int i = 0; i < 4; i++) {
                        const float p = reinterpret_cast<const float*>(&p4[i])[u];
                        acc[i][0] = fmaf(p, va.x, acc[i][0]);
                        acc[i][1] = fmaf(p, va.y, acc[i][1]);
                        acc[i][2] = fmaf(p, va.z, acc[i][2]);
                        acc[i][3] = fmaf(p, va.w, acc[i][3]);
                        acc[i][4] = fmaf(p, vb.x, acc[i][4]);
                        acc[i][5] = fmaf(p, vb.y, acc[i][5]);
                        acc[i][6] = fmaf(p, vb.z, acc[i][6]);
                        acc[i][7] = fmaf(p, vb.w, acc[i][7]);
                    }
                }
            }
        }
        __syncthreads();
    }

    // ---- epilogue: divide by l * sqrt(C), store ----
    #pragma unroll
    for (int i = 0; i < 4; i++) {
        const float inv = 1.f / (s_l[tys*4 + i] * 11.313708499f);  // sqrt(128)
        float* dst = &g_attn[(b*WHQ + q0 + tys*4 + i)*CC + txs*4];
        *reinterpret_cast<float4*>(&dst[0]) =
            make_float4(acc[i][0]*inv, acc[i][1]*inv, acc[i][2]*inv, acc[i][3]*inv);
        *reinterpret_cast<float4*>(&dst[64]) =
            make_float4(acc[i][4]*inv, acc[i][5]*inv, acc[i][6]*inv, acc[i][7]*inv);
    }
}

// ---------------------------------------------------------------------------
// K4: out[b,c,q] = (attn @ Wo + bo)[q,c] * (1+sigmoid(geo[q,c])) + feat0[b,c,q]
// ---------------------------------------------------------------------------
__global__ __launch_bounds__(256) void out_kernel(
    const float* __restrict__ Wo, const float* __restrict__ bo,
    const float* __restrict__ feat0, float* __restrict__ out)
{
    __shared__ float s_A[32][CC + 1];
    const int b  = blockIdx.y;
    const int q0 = blockIdx.x * 32;
    const int tid = threadIdx.x;
    const int tx = tid & 31;       // q
    const int ty = tid >> 5;       // cout group

    #pragma unroll
    for (int i = tid; i < 32*CC; i += 256) {
        int q = i >> 7, c = i & 127;
        s_A[q][c] = g_attn[(b*WHQ + q0 + q)*CC + c];
    }
    __syncthreads();

    float acc[16];
    #pragma unroll
    for (int j = 0; j < 16; j++) acc[j] = bo[ty*16 + j];

    #pragma unroll 4
    for (int c = 0; c < CC; c++) {
        const float a = s_A[tx][c];
        const float4* w4 = reinterpret_cast<const float4*>(&Wo[c*CC + ty*16]);
        #pragma unroll
        for (int j4 = 0; j4 < 4; j4++) {
            float4 w = w4[j4];
            acc[j4*4+0] = fmaf(a, w.x, acc[j4*4+0]);
            acc[j4*4+1] = fmaf(a, w.y, acc[j4*4+1]);
            acc[j4*4+2] = fmaf(a, w.z, acc[j4*4+2]);
            acc[j4*4+3] = fmaf(a, w.w, acc[j4*4+3]);
        }
    }

    #pragma unroll
    for (int j = 0; j < 16; j++) {
        const int cout = ty*16 + j;
        const float g = g_geo[(b*WHQ + q0 + tx)*CC + cout];
        const float sig = 1.f / (1.f + __expf(-g));
        const float v = acc[j]*(1.f + sig) + feat0[(b*CC + cout)*WHQ + q0 + tx];
        out[(b*CC + cout)*WHQ + q0 + tx] = v;
    }
}

// ---------------------------------------------------------------------------
extern "C" void kernel_launch(void* const* d_in, const int* in_sizes, int n_in,
                              void* d_out, int out_size)
{
    const float* feat0     = (const float*)d_in[0];
    const float* feat1     = (const float*)d_in[1];
    const float* geo_embed = (const float*)d_in[2];
    const float* Wq = (const float*)d_in[3];
    const float* bq = (const float*)d_in[4];
    const float* Wk = (const float*)d_in[5];
    const float* bk = (const float*)d_in[6];
    const float* Wv = (const float*)d_in[7];
    const float* bv = (const float*)d_in[8];
    const float* Wo = (const float*)d_in[9];
    const float* bo = (const float*)d_in[10];
    const float* Wg = (const float*)d_in[11];
    const float* bg = (const float*)d_in[12];
    const float* Wgate = (const float*)d_in[13];
    const float* bgate = (const float*)d_in[14];
    float* out = (float*)d_out;

    cudaFuncSetAttribute(attn_kernel,
                         cudaFuncAttributeMaxDynamicSharedMemorySize,
                         ATTN_SMEM_BYTES);

    kv_proj_kernel<<<dim3(NN/32, BB), 256>>>(feat1, Wk, bk, Wv, bv);
    q_geo_kernel<<<dim3(WHQ/32, BB), 256>>>(feat0, geo_embed, Wq, bq, Wg, bg, Wgate, bgate);
    attn_kernel<<<dim3(WHQ/TQ, BB), 256, ATTN_SMEM_BYTES>>>();
    out_kernel<<<dim3(WHQ/32, BB), 256>>>(Wo, bo, feat0, out);
}

// round 3
// speedup vs baseline: 2.3768x; 2.3768x over previous
#include <cuda_runtime.h>
#include <cstdint>

#define BB   8
#define CC   128
#define WHQ  2304
#define NN   8192

#define TQ   64
#define TN   64
#define KSTR 132   // K/Q tile stride: frag loads 4*(lane>>2)+(lane&3) -> conflict-free
#define VSTR 136   // V tile stride:   frag loads 8*(lane&3)+(lane>>2) -> conflict-free
#define SSTR 68    // S tile stride

// Scratch (device globals: allocation-free rule)
__device__ float g_pk  [BB*NN*CC];
__device__ float g_pv  [BB*NN*CC];
__device__ float g_pq  [BB*WHQ*CC];
__device__ float g_geo [BB*WHQ*CC];
__device__ float g_attn[BB*WHQ*CC];

__device__ __forceinline__ float to_tf32(float x) {
    uint32_t u;
    asm("cvt.rna.tf32.f32 %0, %1;" : "=r"(u) : "f"(x));
    return __uint_as_float(u);
}

__device__ __forceinline__ void mma_tf32(float c[4], const uint32_t a[4], uint32_t b0, uint32_t b1) {
    asm volatile(
        "mma.sync.aligned.m16n8k8.row.col.f32.tf32.tf32.f32 "
        "{%0,%1,%2,%3}, {%4,%5,%6,%7}, {%8,%9}, {%0,%1,%2,%3};"
        : "+f"(c[0]), "+f"(c[1]), "+f"(c[2]), "+f"(c[3])
        : "r"(a[0]), "r"(a[1]), "r"(a[2]), "r"(a[3]), "r"(b0), "r"(b1));
}

#define CP_ASYNC16(dst_u32, src_ptr) \
    asm volatile("cp.async.cg.shared.global [%0], [%1], 16;" :: "r"(dst_u32), "l"(src_ptr))
#define CP_COMMIT() asm volatile("cp.async.commit_group;")
#define CP_WAIT1()  asm volatile("cp.async.wait_group 1;")
#define CP_WAIT0()  asm volatile("cp.async.wait_group 0;")

// ---------------------------------------------------------------------------
// K1: pk = feat1^T @ Wk + bk ; pv = feat1^T @ Wv + bv   (tf32-rounded stores)
// ---------------------------------------------------------------------------
__global__ __launch_bounds__(256) void kv_proj_kernel(
    const float* __restrict__ feat1,
    const float* __restrict__ Wk, const float* __restrict__ bk,
    const float* __restrict__ Wv, const float* __restrict__ bv)
{
    __shared__ float s_in[32][CC + 1];
    const int b  = blockIdx.y;
    const int n0 = blockIdx.x * 32;
    const int tid = threadIdx.x;
    const int tx = tid & 31;
    const int ty = tid >> 5;

    #pragma unroll
    for (int c = ty; c < CC; c += 8)
        s_in[tx][c] = feat1[(b*CC + c)*NN + n0 + tx];
    __syncthreads();

    float accK[16], accV[16];
    #pragma unroll
    for (int j = 0; j < 16; j++) { accK[j] = bk[ty*16 + j]; accV[j] = bv[ty*16 + j]; }

    #pragma unroll 4
    for (int c = 0; c < CC; c++) {
        const float a = s_in[tx][c];
        const float4* wk4 = reinterpret_cast<const float4*>(&Wk[c*CC + ty*16]);
        const float4* wv4 = reinterpret_cast<const float4*>(&Wv[c*CC + ty*16]);
        #pragma unroll
        for (int j4 = 0; j4 < 4; j4++) {
            float4 k4 = wk4[j4];
            float4 v4 = wv4[j4];
            accK[j4*4+0] = fmaf(a, k4.x, accK[j4*4+0]);
            accK[j4*4+1] = fmaf(a, k4.y, accK[j4*4+1]);
            accK[j4*4+2] = fmaf(a, k4.z, accK[j4*4+2]);
            accK[j4*4+3] = fmaf(a, k4.w, accK[j4*4+3]);
            accV[j4*4+0] = fmaf(a, v4.x, accV[j4*4+0]);
            accV[j4*4+1] = fmaf(a, v4.y, accV[j4*4+1]);
            accV[j4*4+2] = fmaf(a, v4.z, accV[j4*4+2]);
            accV[j4*4+3] = fmaf(a, v4.w, accV[j4*4+3]);
        }
    }

    const int base = (b*NN + n0 + tx)*CC + ty*16;
    #pragma unroll
    for (int j4 = 0; j4 < 4; j4++) {
        *reinterpret_cast<float4*>(&g_pk[base + j4*4]) =
            make_float4(to_tf32(accK[j4*4+0]), to_tf32(accK[j4*4+1]),
                        to_tf32(accK[j4*4+2]), to_tf32(accK[j4*4+3]));
        *reinterpret_cast<float4*>(&g_pv[base + j4*4]) =
            make_float4(to_tf32(accV[j4*4+0]), to_tf32(accV[j4*4+1]),
                        to_tf32(accV[j4*4+2]), to_tf32(accV[j4*4+3]));
    }
}

// ---------------------------------------------------------------------------
// K2: pq (gated) + geo  (pq tf32-rounded; geo kept exact for epilogue)
// ---------------------------------------------------------------------------
__global__ __launch_bounds__(256) void q_geo_kernel(
    const float* __restrict__ feat0, const float* __restrict__ geo_embed,
    const float* __restrict__ Wq, const float* __restrict__ bq,
    const float* __restrict__ Wg, const float* __restrict__ bg,
    const float* __restrict__ Wgate, const float* __restrict__ bgate)
{
    __shared__ float s_q[32][CC + 1];
    __shared__ float s_g[32][CC + 1];
    __shared__ float s_part[8][32];
    __shared__ float s_gate[32];

    const int b  = blockIdx.y;
    const int q0 = blockIdx.x * 32;
    const int tid = threadIdx.x;
    const int tx = tid & 31;
    const int ty = tid >> 5;

    #pragma unroll
    for (int c = ty; c < CC; c += 8)
        s_q[tx][c] = feat0[(b*CC + c)*WHQ + q0 + tx];
    #pragma unroll
    for (int i = tid; i < 32*CC; i += 256) {
        int q = i >> 7, c = i & 127;
        s_g[q][c] = geo_embed[(b*WHQ + q0 + q)*CC + c];
    }
    __syncthreads();

    float aq[16], ag[16];
    #pragma unroll
    for (int j = 0; j < 16; j++) { aq[j] = bq[ty*16 + j]; ag[j] = bg[ty*16 + j]; }

    #pragma unroll 4
    for (int c = 0; c < CC; c++) {
        const float xq = s_q[tx][c];
        const float xg = s_g[tx][c];
        const float4* wq4 = reinterpret_cast<const float4*>(&Wq[c*CC + ty*16]);
        const float4* wg4 = reinterpret_cast<const float4*>(&Wg[c*CC + ty*16]);
        #pragma unroll
        for (int j4 = 0; j4 < 4; j4++) {
            float4 q4 = wq4[j4];
            float4 g4 = wg4[j4];
            aq[j4*4+0] = fmaf(xq, q4.x, aq[j4*4+0]);
            aq[j4*4+1] = fmaf(xq, q4.y, aq[j4*4+1]);
            aq[j4*4+2] = fmaf(xq, q4.z, aq[j4*4+2]);
            aq[j4*4+3] = fmaf(xq, q4.w, aq[j4*4+3]);
            ag[j4*4+0] = fmaf(xg, g4.x, ag[j4*4+0]);
            ag[j4*4+1] = fmaf(xg, g4.y, ag[j4*4+1]);
            ag[j4*4+2] = fmaf(xg, g4.z, ag[j4*4+2]);
            ag[j4*4+3] = fmaf(xg, g4.w, ag[j4*4+3]);
        }
    }

    float part = 0.f;
    #pragma unroll
    for (int j = 0; j < 16; j++)
        part += aq[j]*Wgate[ty*16 + j] + ag[j]*Wgate[CC + ty*16 + j];
    s_part[ty][tx] = part;
    __syncthreads();
    if (ty == 0) {
        float s = bgate[0];
        #pragma unroll
        for (int k = 0; k < 8; k++) s += s_part[k][tx];
        s_gate[tx] = 1.f / (1.f + __expf(-s));
    }
    __syncthreads();
    const float gate = s_gate[tx];

    const int base = (b*WHQ + q0 + tx)*CC + ty*16;
    #pragma unroll
    for (int j4 = 0; j4 < 4; j4++) {
        *reinterpret_cast<float4*>(&g_pq[base + j4*4]) =
            make_float4(to_tf32(aq[j4*4+0] + gate*ag[j4*4+0]),
                        to_tf32(aq[j4*4+1] + gate*ag[j4*4+1]),
                        to_tf32(aq[j4*4+2] + gate*ag[j4*4+2]),
                        to_tf32(aq[j4*4+3] + gate*ag[j4*4+3]));
        *reinterpret_cast<float4*>(&g_geo[base + j4*4]) =
            make_float4(ag[j4*4+0], ag[j4*4+1], ag[j4*4+2], ag[j4*4+3]);
    }
}

// ---------------------------------------------------------------------------
// K3: flash attention with mma.sync tf32 tensor cores.
//     8 warps (4M x 2N), Q fragments register-resident, cp.async K/V pipeline.
// ---------------------------------------------------------------------------
#define KOFF0 0
#define KOFF1 (TQ*KSTR)
#define VOFF0 (2*TQ*KSTR)
#define VOFF1 (2*TQ*KSTR + TN*VSTR)
#define SOFF  (2*TQ*KSTR + 2*TN*VSTR)
#define MOFF  (SOFF + TQ*SSTR)
#define ATTN_SMEM_FLOATS (MOFF + 3*TQ)
#define ATTN_SMEM_BYTES  (ATTN_SMEM_FLOATS * 4)

__global__ void __launch_bounds__(256, 1) attn_kernel()
{
    extern __shared__ float sm[];
    const uint32_t smem_u32 = (uint32_t)__cvta_generic_to_shared(sm);

    const int b   = blockIdx.y;
    const int q0  = blockIdx.x * TQ;
    const int tid = threadIdx.x;
    const int lane = tid & 31;
    const int wid  = tid >> 5;
    const int wm   = wid & 3;        // M group: rows 16*wm .. +15
    const int wn   = wid >> 2;       // N group
    const int l4   = lane & 3;
    const int ld   = lane >> 2;
    const int r0   = 16*wm + ld;     // this thread's base row (and r0+8)

    const float* gk = g_pk + (size_t)b*NN*CC;
    const float* gv = g_pv + (size_t)b*NN*CC;

    // ---- stage Q into K-buffer 1, extract A-fragments into registers ----
    {
        const float4* src = reinterpret_cast<const float4*>(&g_pq[(size_t)(b*WHQ + q0)*CC]);
        #pragma unroll
        for (int i = tid; i < TQ*CC/4; i += 256) {
            int r = i >> 5, c4 = i & 31;
            *reinterpret_cast<float4*>(&sm[KOFF1 + r*KSTR + c4*4]) = src[i];
        }
    }
    __syncthreads();
    uint32_t qa[16][4];
    #pragma unroll
    for (int kc = 0; kc < 16; kc++) {
        const int c0 = 8*kc + l4;
        qa[kc][0] = __float_as_uint(sm[KOFF1 + (r0    )*KSTR + c0    ]);
        qa[kc][1] = __float_as_uint(sm[KOFF1 + (r0 + 8)*KSTR + c0    ]);
        qa[kc][2] = __float_as_uint(sm[KOFF1 + (r0    )*KSTR + c0 + 4]);
        qa[kc][3] = __float_as_uint(sm[KOFF1 + (r0 + 8)*KSTR + c0 + 4]);
    }
    if (tid < TQ) { sm[MOFF + tid] = -1e30f; sm[MOFF + TQ + tid] = 0.f; }
    __syncthreads();

    float oacc[8][4];
    #pragma unroll
    for (int nt = 0; nt < 8; nt++)
        #pragma unroll
        for (int j = 0; j < 4; j++) oacc[nt][j] = 0.f;

    // ---- cp.async helpers: 8 float4 per thread per tile for K and for V ----
    const int ln = tid >> 5;   // row within the 8-row slab this thread loads
    const int lc = tid & 31;   // float4 column
    // prologue: tile 0 -> buffer 0
    {
        #pragma unroll
        for (int j = 0; j < 8; j++) {
            int n = j*8 + ln;
            CP_ASYNC16(smem_u32 + (KOFF0 + n*KSTR + lc*4)*4, gk + (size_t)n*CC + lc*4);
            CP_ASYNC16(smem_u32 + (VOFF0 + n*VSTR + lc*4)*4, gv + (size_t)n*CC + lc*4);
        }
        CP_COMMIT();
    }

    const int NT = NN / TN;  // 128
    for (int t = 0; t < NT; ++t) {
        if (t + 1 < NT) {
            const float* gkn = gk + (size_t)(t+1)*TN*CC;
            const float* gvn = gv + (size_t)(t+1)*TN*CC;
            const int kb = ((t+1) & 1) ? KOFF1 : KOFF0;
            const int vb = ((t+1) & 1) ? VOFF1 : VOFF0;
            #pragma unroll
            for (int j = 0; j < 8; j++) {
                int n = j*8 + ln;
                CP_ASYNC16(smem_u32 + (kb + n*KSTR + lc*4)*4, gkn + (size_t)n*CC + lc*4);
                CP_ASYNC16(smem_u32 + (vb + n*VSTR + lc*4)*4, gvn + (size_t)n*CC + lc*4);
            }
            CP_COMMIT();
            CP_WAIT1();
        } else {
            CP_WAIT0();
        }
        __syncthreads();

        const int kb = (t & 1) ? KOFF1 : KOFF0;
        const int vb = (t & 1) ? VOFF1 : VOFF0;

        // ---- S = Q @ K^T (tensor cores) ----
        float sacc[4][4];
        #pragma unroll
        for (int nt = 0; nt < 4; nt++)
            #pragma unroll
            for (int j = 0; j < 4; j++) sacc[nt][j] = 0.f;

        #pragma unroll
        for (int kc = 0; kc < 16; kc++) {
            const int c0 = 8*kc + l4;
            uint32_t bk0[4], bk1[4];
            #pragma unroll
            for (int nt = 0; nt < 4; nt++) {
                const int n = 32*wn + 8*nt + ld;
                bk0[nt] = __float_as_uint(sm[kb + n*KSTR + c0    ]);
                bk1[nt] = __float_as_uint(sm[kb + n*KSTR + c0 + 4]);
            }
            #pragma unroll
            for (int nt = 0; nt < 4; nt++)
                mma_tf32(sacc[nt], qa[kc], bk0[nt], bk1[nt]);
        }
        #pragma unroll
        for (int nt = 0; nt < 4; nt++) {
            const int col = 32*wn + 8*nt + 2*l4;
            *reinterpret_cast<float2*>(&sm[SOFF + (r0    )*SSTR + col]) =
                make_float2(sacc[nt][0], sacc[nt][1]);
            *reinterpret_cast<float2*>(&sm[SOFF + (r0 + 8)*SSTR + col]) =
                make_float2(sacc[nt][2], sacc[nt][3]);
        }
        __syncthreads();

        // ---- online softmax (4 threads per row) ----
        {
            const int r = tid >> 2, sub = tid & 3;
            float mloc = -1e30f;
            #pragma unroll
            for (int k = 0; k < 16; k++)
                mloc = fmaxf(mloc, sm[SOFF + r*SSTR + sub + 4*k]);
            mloc = fmaxf(mloc, __shfl_xor_sync(0xffffffffu, mloc, 1));
            mloc = fmaxf(mloc, __shfl_xor_sync(0xffffffffu, mloc, 2));
            const float mold = sm[MOFF + r];
            const float mnew = fmaxf(mold, mloc);
            float sum = 0.f;
            #pragma unroll
            for (int k = 0; k < 16; k++) {
                float p = __expf(sm[SOFF + r*SSTR + sub + 4*k] - mnew);
                sm[SOFF + r*SSTR + sub + 4*k] = p;
                sum += p;
            }
            sum += __shfl_xor_sync(0xffffffffu, sum, 1);
            sum += __shfl_xor_sync(0xffffffffu, sum, 2);
            if (sub == 0) {
                const float alpha = __expf(mold - mnew);
                sm[MOFF + r] = mnew;
                sm[MOFF + TQ + r]   = sm[MOFF + TQ + r]*alpha + sum;
                sm[MOFF + 2*TQ + r] = alpha;
            }
        }
        __syncthreads();

        // ---- rescale O, O += P @ V (tensor cores) ----
        {
            const float al0 = sm[MOFF + 2*TQ + r0];
            const float al1 = sm[MOFF + 2*TQ + r0 + 8];
            #pragma unroll
            for (int nt = 0; nt < 8; nt++) {
                oacc[nt][0] *= al0; oacc[nt][1] *= al0;
                oacc[nt][2] *= al1; oacc[nt][3] *= al1;
            }
            #pragma unroll
            for (int kc = 0; kc < 8; kc++) {
                const int c0 = 8*kc + l4;
                uint32_t pa[4];
                pa[0] = __float_as_uint(sm[SOFF + (r0    )*SSTR + c0    ]);
                pa[1] = __float_as_uint(sm[SOFF + (r0 + 8)*SSTR + c0    ]);
                pa[2] = __float_as_uint(sm[SOFF + (r0    )*SSTR + c0 + 4]);
                pa[3] = __float_as_uint(sm[SOFF + (r0 + 8)*SSTR + c0 + 4]);
                const int k0 = 8*kc;
                #pragma unroll
                for (int nt = 0; nt < 8; nt++) {
                    const int cb = 64*wn + 8*nt + ld;
                    uint32_t v0 = __float_as_uint(sm[vb + (k0 + l4    )*VSTR + cb]);
                    uint32_t v1 = __float_as_uint(sm[vb + (k0 + l4 + 4)*VSTR + cb]);
                    mma_tf32(oacc[nt], pa, v0, v1);
                }
            }
        }
        __syncthreads();
    }

    // ---- epilogue: divide by l * sqrt(C), store ----
    const float inv0 = 1.f / (sm[MOFF + TQ + r0    ] * 11.313708499f);
    const float inv1 = 1.f / (sm[MOFF + TQ + r0 + 8] * 11.313708499f);
    #pragma unroll
    for (int nt = 0; nt < 8; nt++) {
        const int col = 64*wn + 8*nt + 2*l4;
        *reinterpret_cast<float2*>(&g_attn[(size_t)(b*WHQ + q0 + r0)*CC + col]) =
            make_float2(oacc[nt][0]*inv0, oacc[nt][1]*inv0);
        *reinterpret_cast<float2*>(&g_attn[(size_t)(b*WHQ + q0 + r0 + 8)*CC + col]) =
            make_float2(oacc[nt][2]*inv1, oacc[nt][3]*inv1);
    }
}

// ---------------------------------------------------------------------------
// K4: out = (attn @ Wo + bo) * (1+sigmoid(geo)) + feat0, transposed store
// ---------------------------------------------------------------------------
__global__ __launch_bounds__(256) void out_kernel(
    const float* __restrict__ Wo, const float* __restrict__ bo,
    const float* __restrict__ feat0, float* __restrict__ out)
{
    __shared__ float s_A[32][CC + 1];
    const int b  = blockIdx.y;
    const int q0 = blockIdx.x * 32;
    const int tid = threadIdx.x;
    const int tx = tid & 31;
    const int ty = tid >> 5;

    #pragma unroll
    for (int i = tid; i < 32*CC; i += 256) {
        int q = i >> 7, c = i & 127;
        s_A[q][c] = g_attn[(b*WHQ + q0 + q)*CC + c];
    }
    __syncthreads();

    float acc[16];
    #pragma unroll
    for (int j = 0; j < 16; j++) acc[j] = bo[ty*16 + j];

    #pragma unroll 4
    for (int c = 0; c < CC; c++) {
        const float a = s_A[tx][c];
        const float4* w4 = reinterpret_cast<const float4*>(&Wo[c*CC + ty*16]);
        #pragma unroll
        for (int j4 = 0; j4 < 4; j4++) {
            float4 w = w4[j4];
            acc[j4*4+0] = fmaf(a, w.x, acc[j4*4+0]);
            acc[j4*4+1] = fmaf(a, w.y, acc[j4*4+1]);
            acc[j4*4+2] = fmaf(a, w.z, acc[j4*4+2]);
            acc[j4*4+3] = fmaf(a, w.w, acc[j4*4+3]);
        }
    }

    #pragma unroll
    for (int j = 0; j < 16; j++) {
        const int cout = ty*16 + j;
        const float g = g_geo[(b*WHQ + q0 + tx)*CC + cout];
        const float sig = 1.f / (1.f + __expf(-g));
        const float v = acc[j]*(1.f + sig) + feat0[(b*CC + cout)*WHQ + q0 + tx];
        out[(b*CC + cout)*WHQ + q0 + tx] = v;
    }
}

// ---------------------------------------------------------------------------
extern "C" void kernel_launch(void* const* d_in, const int* in_sizes, int n_in,
                              void* d_out, int out_size)
{
    const float* feat0     = (const float*)d_in[0];
    const float* feat1     = (const float*)d_in[1];
    const float* geo_embed = (const float*)d_in[2];
    const float* Wq = (const float*)d_in[3];
    const float* bq = (const float*)d_in[4];
    const float* Wk = (const float*)d_in[5];
    const float* bk = (const float*)d_in[6];
    const float* Wv = (const float*)d_in[7];
    const float* bv = (const float*)d_in[8];
    const float* Wo = (const float*)d_in[9];
    const float* bo = (const float*)d_in[10];
    const float* Wg = (const float*)d_in[11];
    const float* bg = (const float*)d_in[12];
    const float* Wgate = (const float*)d_in[13];
    const float* bgate = (const float*)d_in[14];
    float* out = (float*)d_out;

    cudaFuncSetAttribute(attn_kernel,
                         cudaFuncAttributeMaxDynamicSharedMemorySize,
                         ATTN_SMEM_BYTES);

    kv_proj_kernel<<<dim3(NN/32, BB), 256>>>(feat1, Wk, bk, Wv, bv);
    q_geo_kernel<<<dim3(WHQ/32, BB), 256>>>(feat0, geo_embed, Wq, bq, Wg, bg, Wgate, bgate);
    attn_kernel<<<dim3(WHQ/TQ, BB), 256, ATTN_SMEM_BYTES>>>();
    out_kernel<<<dim3(WHQ/32, BB), 256>>>(Wo, bo, feat0, out);
}

// round 5
// speedup vs baseline: 3.0481x; 1.2825x over previous
#include <cuda_runtime.h>
#include <cuda_bf16.h>
#include <cstdint>

#define BB   8
#define CC   128
#define WHQ  2304
#define NN   8192

#define TQ   64
#define TN   64
#define NT   (NN/TN)
#define KSTR 132     // K tile stride (floats)
#define VSTRH 72     // V^T tile stride (halves): rows start 16B apart mod 128 -> conflict-free

// Scratch (device globals: allocation-free rule)
__device__ float         g_pk  [BB*NN*CC];   // [b, n, c] tf32
__device__ __nv_bfloat16 g_pvT [BB*CC*NN];   // [b, c, n] bf16 (V transposed)
__device__ float         g_pq  [BB*WHQ*CC];
__device__ float         g_geo [BB*WHQ*CC];
__device__ float         g_attn[BB*WHQ*CC];

__device__ __forceinline__ float to_tf32(float x) {
    uint32_t u;
    asm("cvt.rna.tf32.f32 %0, %1;" : "=r"(u) : "f"(x));
    return __uint_as_float(u);
}

__device__ __forceinline__ void mma_tf32(float c[4], const uint32_t a[4], uint32_t b0, uint32_t b1) {
    asm volatile(
        "mma.sync.aligned.m16n8k8.row.col.f32.tf32.tf32.f32 "
        "{%0,%1,%2,%3}, {%4,%5,%6,%7}, {%8,%9}, {%0,%1,%2,%3};"
        : "+f"(c[0]), "+f"(c[1]), "+f"(c[2]), "+f"(c[3])
        : "r"(a[0]), "r"(a[1]), "r"(a[2]), "r"(a[3]), "r"(b0), "r"(b1));
}

__device__ __forceinline__ void mma_bf16(float c[4], const uint32_t a[4], uint32_t b0, uint32_t b1) {
    asm volatile(
        "mma.sync.aligned.m16n8k16.row.col.f32.bf16.bf16.f32 "
        "{%0,%1,%2,%3}, {%4,%5,%6,%7}, {%8,%9}, {%0,%1,%2,%3};"
        : "+f"(c[0]), "+f"(c[1]), "+f"(c[2]), "+f"(c[3])
        : "r"(a[0]), "r"(a[1]), "r"(a[2]), "r"(a[3]), "r"(b0), "r"(b1));
}

// d = {hi = a, lo = b}
__device__ __forceinline__ uint32_t pack_bf16(float hi, float lo) {
    uint32_t r;
    asm("cvt.rn.bf16x2.f32 %0, %1, %2;" : "=r"(r) : "f"(hi), "f"(lo));
    return r;
}

#define CP_ASYNC16(dst_u32, src_ptr) \
    asm volatile("cp.async.cg.shared.global [%0], [%1], 16;" :: "r"(dst_u32), "l"(src_ptr))
#define CP_COMMIT() asm volatile("cp.async.commit_group;")
#define CP_WAIT0()  asm volatile("cp.async.wait_group 0;" ::: "memory")

// ---------------------------------------------------------------------------
// K1: pk = feat1^T @ Wk + bk (tf32, [b,n,c]); pvT = (feat1^T @ Wv + bv)^T bf16
// ---------------------------------------------------------------------------
__global__ __launch_bounds__(256) void kv_proj_kernel(
    const float* __restrict__ feat1,
    const float* __restrict__ Wk, const float* __restrict__ bk,
    const float* __restrict__ Wv, const float* __restrict__ bv)
{
    __shared__ float s_in[32][CC + 1];
    const int b  = blockIdx.y;
    const int n0 = blockIdx.x * 32;
    const int tid = threadIdx.x;
    const int tx = tid & 31;
    const int ty = tid >> 5;

    #pragma unroll
    for (int c = ty; c < CC; c += 8)
        s_in[tx][c] = feat1[(b*CC + c)*NN + n0 + tx];
    __syncthreads();

    float accK[16], accV[16];
    #pragma unroll
    for (int j = 0; j < 16; j++) { accK[j] = bk[ty*16 + j]; accV[j] = bv[ty*16 + j]; }

    #pragma unroll 4
    for (int c = 0; c < CC; c++) {
        const float a = s_in[tx][c];
        const float4* wk4 = reinterpret_cast<const float4*>(&Wk[c*CC + ty*16]);
        const float4* wv4 = reinterpret_cast<const float4*>(&Wv[c*CC + ty*16]);
        #pragma unroll
        for (int j4 = 0; j4 < 4; j4++) {
            float4 k4 = wk4[j4];
            float4 v4 = wv4[j4];
            accK[j4*4+0] = fmaf(a, k4.x, accK[j4*4+0]);
            accK[j4*4+1] = fmaf(a, k4.y, accK[j4*4+1]);
            accK[j4*4+2] = fmaf(a, k4.z, accK[j4*4+2]);
            accK[j4*4+3] = fmaf(a, k4.w, accK[j4*4+3]);
            accV[j4*4+0] = fmaf(a, v4.x, accV[j4*4+0]);
            accV[j4*4+1] = fmaf(a, v4.y, accV[j4*4+1]);
            accV[j4*4+2] = fmaf(a, v4.z, accV[j4*4+2]);
            accV[j4*4+3] = fmaf(a, v4.w, accV[j4*4+3]);
        }
    }

    const int base = (b*NN + n0 + tx)*CC + ty*16;
    #pragma unroll
    for (int j4 = 0; j4 < 4; j4++)
        *reinterpret_cast<float4*>(&g_pk[base + j4*4]) =
            make_float4(to_tf32(accK[j4*4+0]), to_tf32(accK[j4*4+1]),
                        to_tf32(accK[j4*4+2]), to_tf32(accK[j4*4+3]));
    #pragma unroll
    for (int j = 0; j < 16; j++)
        g_pvT[(size_t)(b*CC + ty*16 + j)*NN + n0 + tx] = __float2bfloat16(accV[j]);
}

// ---------------------------------------------------------------------------
// K2: pq (gated, tf32-rounded) + geo (exact)
// ---------------------------------------------------------------------------
__global__ __launch_bounds__(256) void q_geo_kernel(
    const float* __restrict__ feat0, const float* __restrict__ geo_embed,
    const float* __restrict__ Wq, const float* __restrict__ bq,
    const float* __restrict__ Wg, const float* __restrict__ bg,
    const float* __restrict__ Wgate, const float* __restrict__ bgate)
{
    __shared__ float s_q[32][CC + 1];
    __shared__ float s_g[32][CC + 1];
    __shared__ float s_part[8][32];
    __shared__ float s_gate[32];

    const int b  = blockIdx.y;
    const int q0 = blockIdx.x * 32;
    const int tid = threadIdx.x;
    const int tx = tid & 31;
    const int ty = tid >> 5;

    #pragma unroll
    for (int c = ty; c < CC; c += 8)
        s_q[tx][c] = feat0[(b*CC + c)*WHQ + q0 + tx];
    #pragma unroll
    for (int i = tid; i < 32*CC; i += 256) {
        int q = i >> 7, c = i & 127;
        s_g[q][c] = geo_embed[(b*WHQ + q0 + q)*CC + c];
    }
    __syncthreads();

    float aq[16], ag[16];
    #pragma unroll
    for (int j = 0; j < 16; j++) { aq[j] = bq[ty*16 + j]; ag[j] = bg[ty*16 + j]; }

    #pragma unroll 4
    for (int c = 0; c < CC; c++) {
        const float xq = s_q[tx][c];
        const float xg = s_g[tx][c];
        const float4* wq4 = reinterpret_cast<const float4*>(&Wq[c*CC + ty*16]);
        const float4* wg4 = reinterpret_cast<const float4*>(&Wg[c*CC + ty*16]);
        #pragma unroll
        for (int j4 = 0; j4 < 4; j4++) {
            float4 q4 = wq4[j4];
            float4 g4 = wg4[j4];
            aq[j4*4+0] = fmaf(xq, q4.x, aq[j4*4+0]);
            aq[j4*4+1] = fmaf(xq, q4.y, aq[j4*4+1]);
            aq[j4*4+2] = fmaf(xq, q4.z, aq[j4*4+2]);
            aq[j4*4+3] = fmaf(xq, q4.w, aq[j4*4+3]);
            ag[j4*4+0] = fmaf(xg, g4.x, ag[j4*4+0]);
            ag[j4*4+1] = fmaf(xg, g4.y, ag[j4*4+1]);
            ag[j4*4+2] = fmaf(xg, g4.z, ag[j4*4+2]);
            ag[j4*4+3] = fmaf(xg, g4.w, ag[j4*4+3]);
        }
    }

    float part = 0.f;
    #pragma unroll
    for (int j = 0; j < 16; j++)
        part += aq[j]*Wgate[ty*16 + j] + ag[j]*Wgate[CC + ty*16 + j];
    s_part[ty][tx] = part;
    __syncthreads();
    if (ty == 0) {
        float s = bgate[0];
        #pragma unroll
        for (int k = 0; k < 8; k++) s += s_part[k][tx];
        s_gate[tx] = 1.f / (1.f + __expf(-s));
    }
    __syncthreads();
    const float gate = s_gate[tx];

    const int base = (b*WHQ + q0 + tx)*CC + ty*16;
    #pragma unroll
    for (int j4 = 0; j4 < 4; j4++) {
        *reinterpret_cast<float4*>(&g_pq[base + j4*4]) =
            make_float4(to_tf32(aq[j4*4+0] + gate*ag[j4*4+0]),
                        to_tf32(aq[j4*4+1] + gate*ag[j4*4+1]),
                        to_tf32(aq[j4*4+2] + gate*ag[j4*4+2]),
                        to_tf32(aq[j4*4+3] + gate*ag[j4*4+3]));
        *reinterpret_cast<float4*>(&g_geo[base + j4*4]) =
            make_float4(ag[j4*4+0], ag[j4*4+1], ag[j4*4+2], ag[j4*4+3]);
    }
}

// ---------------------------------------------------------------------------
// K3: flash attention, P register-resident.
//   8 warps: wm=wid&3 (rows 16wm..+15), wn=wid>>2 (S cols / PV split-K half).
//   QK: tf32 m16n8k8, Q frags in regs. PV: bf16 m16n8k16, P packed in regs,
//   V^T bf16 in smem. Fixed per-row m0 from tile 0; l in registers.
// ---------------------------------------------------------------------------
#define SM_K0B 0
#define SM_K1B (TQ*KSTR*4)
#define SM_V0B (2*TQ*KSTR*4)
#define SM_V1B (SM_V0B + CC*VSTRH*2)
#define SM_MXB (SM_V0B + 2*CC*VSTRH*2)     // 128 floats
#define SM_LWB (SM_MXB + 512)              // 128 floats
#define ATTN_SMEM_BYTES (SM_LWB + 512)

__global__ void __launch_bounds__(256, 1) attn_kernel()
{
    extern __shared__ __align__(128) char smc[];
    float* smf = reinterpret_cast<float*>(smc);
    const uint32_t smem_u32 = (uint32_t)__cvta_generic_to_shared(smc);

    const int b   = blockIdx.y;
    const int q0  = blockIdx.x * TQ;
    const int tid = threadIdx.x;
    const int lane = tid & 31;
    const int wid  = tid >> 5;
    const int wm   = wid & 3;
    const int wn   = wid >> 2;
    const int l4   = lane & 3;
    const int ld   = lane >> 2;
    const int r0   = 16*wm + ld;

    float* s_mx = smf + SM_MXB/4;   // [2][64]
    float* s_lw = smf + SM_LWB/4;   // [2][64]

    const float* gk = g_pk + (size_t)b*NN*CC;
    const __nv_bfloat16* gvT = g_pvT + (size_t)b*CC*NN;

    // ---- stage Q into K-buffer 1, extract A-fragments ----
    {
        const float4* src = reinterpret_cast<const float4*>(&g_pq[(size_t)(b*WHQ + q0)*CC]);
        #pragma unroll
        for (int i = tid; i < TQ*CC/4; i += 256) {
            int r = i >> 5, c4 = i & 31;
            *reinterpret_cast<float4*>(&smf[TQ*KSTR + r*KSTR + c4*4]) = src[i];
        }
    }
    __syncthreads();
    uint32_t qa[16][4];
    #pragma unroll
    for (int kc = 0; kc < 16; kc++) {
        const int c0 = 8*kc + l4;
        qa[kc][0] = __float_as_uint(smf[TQ*KSTR + (r0    )*KSTR + c0    ]);
        qa[kc][1] = __float_as_uint(smf[TQ*KSTR + (r0 + 8)*KSTR + c0    ]);
        qa[kc][2] = __float_as_uint(smf[TQ*KSTR + (r0    )*KSTR + c0 + 4]);
        qa[kc][3] = __float_as_uint(smf[TQ*KSTR + (r0 + 8)*KSTR + c0 + 4]);
    }

    // ---- tile loader (K tf32 32KB, V^T bf16 16KB per tile) ----
    auto load_tile = [&](int t, int buf) {
        const uint32_t kb = smem_u32 + (buf ? SM_K1B : SM_K0B);
        const uint32_t vb = smem_u32 + (buf ? SM_V1B : SM_V0B);
        const float* ksrc = gk + (size_t)t*TN*CC;
        #pragma unroll
        for (int j = 0; j < 8; j++) {
            int idx = j*256 + tid;
            int r = idx >> 5, c4 = idx & 31;
            CP_ASYNC16(kb + (uint32_t)(r*KSTR*4 + c4*16), ksrc + (size_t)r*CC + c4*4);
        }
        #pragma unroll
        for (int j = 0; j < 4; j++) {
            int idx = j*256 + tid;
            int c = idx >> 3, ck = idx & 7;
            CP_ASYNC16(vb + (uint32_t)(c*VSTRH*2 + ck*16),
                       gvT + (size_t)c*NN + (size_t)t*TN + ck*8);
        }
        CP_COMMIT();
    };

    load_tile(0, 0);

    float oacc[16][4];
    #pragma unroll
    for (int i = 0; i < 16; i++)
        #pragma unroll
        for (int j = 0; j < 4; j++) oacc[i][j] = 0.f;
    float l_acc0 = 0.f, l_acc1 = 0.f;
    float m0a = 0.f, m0b = 0.f;

    for (int t = 0; t < NT; ++t) {
        CP_WAIT0();
        __syncthreads();                       // tile t visible; all PV(t-1) done
        if (t + 1 < NT) load_tile(t+1, (t+1)&1);

        const int kbf = (t & 1) ? TQ*KSTR : 0;                   // floats
        const uint32_t vbB = (uint32_t)((t & 1) ? SM_V1B : SM_V0B); // bytes

        // ---- S = Q @ K^T (tf32 tensor cores) ----
        float sacc[4][4];
        #pragma unroll
        for (int nt = 0; nt < 4; nt++)
            #pragma unroll
            for (int j = 0; j < 4; j++) sacc[nt][j] = 0.f;

        #pragma unroll
        for (int kc = 0; kc < 16; kc++) {
            const int c0 = 8*kc + l4;
            uint32_t bk0[4], bk1[4];
            #pragma unroll
            for (int nt = 0; nt < 4; nt++) {
                const int n = 32*wn + 8*nt + ld;
                bk0[nt] = __float_as_uint(smf[kbf + n*KSTR + c0    ]);
                bk1[nt] = __float_as_uint(smf[kbf + n*KSTR + c0 + 4]);
            }
            #pragma unroll
            for (int nt = 0; nt < 4; nt++)
                mma_tf32(sacc[nt], qa[kc], bk0[nt], bk1[nt]);
        }

        // ---- per-row m0 from tile 0 only ----
        if (t == 0) {
            float mx0 = -1e30f, mx1 = -1e30f;
            #pragma unroll
            for (int nt = 0; nt < 4; nt++) {
                mx0 = fmaxf(mx0, fmaxf(sacc[nt][0], sacc[nt][1]));
                mx1 = fmaxf(mx1, fmaxf(sacc[nt][2], sacc[nt][3]));
            }
            mx0 = fmaxf(mx0, __shfl_xor_sync(0xffffffffu, mx0, 1));
            mx0 = fmaxf(mx0, __shfl_xor_sync(0xffffffffu, mx0, 2));
            mx1 = fmaxf(mx1, __shfl_xor_sync(0xffffffffu, mx1, 1));
            mx1 = fmaxf(mx1, __shfl_xor_sync(0xffffffffu, mx1, 2));
            if (l4 == 0) { s_mx[wn*64 + r0] = mx0; s_mx[wn*64 + r0 + 8] = mx1; }
            __syncthreads();
            m0a = fmaxf(s_mx[r0],     s_mx[64 + r0]);
            m0b = fmaxf(s_mx[r0 + 8], s_mx[64 + r0 + 8]);
        }

        // ---- exp + pack P (registers), accumulate l ----
        uint32_t pa[2][4];
        float ls0 = 0.f, ls1 = 0.f;
        #pragma unroll
        for (int nt = 0; nt < 4; nt++) {
            float p0 = __expf(sacc[nt][0] - m0a);
            float p1 = __expf(sacc[nt][1] - m0a);
            float p2 = __expf(sacc[nt][2] - m0b);
            float p3 = __expf(sacc[nt][3] - m0b);
            ls0 += p0 + p1;
            ls1 += p2 + p3;
            const int kc = nt >> 1, o = (nt & 1) ? 2 : 0;
            pa[kc][o + 0] = pack_bf16(p1, p0);
            pa[kc][o + 1] = pack_bf16(p3, p2);
        }
        l_acc0 += ls0;
        l_acc1 += ls1;

        // ---- O += P @ V (bf16 tensor cores, split-K over wn) ----
        #pragma unroll
        for (int kc = 0; kc < 2; kc++) {
            const int kbase = 32*wn + 16*kc + 2*l4;   // halves
            #pragma unroll
            for (int nt = 0; nt < 16; nt++) {
                const int c = 8*nt + ld;
                const uint32_t off = vbB + (uint32_t)(c*VSTRH + kbase)*2;
                uint32_t v0 = *reinterpret_cast<const uint32_t*>(smc + off);
                uint32_t v1 = *reinterpret_cast<const uint32_t*>(smc + off + 16);
                mma_bf16(oacc[nt], pa[kc], v0, v1);
            }
        }
    }

    // ---- epilogue: reduce l, merge wn partials, scale, store ----
    l_acc0 += __shfl_xor_sync(0xffffffffu, l_acc0, 1);
    l_acc0 += __shfl_xor_sync(0xffffffffu, l_acc0, 2);
    l_acc1 += __shfl_xor_sync(0xffffffffu, l_acc1, 1);
    l_acc1 += __shfl_xor_sync(0xffffffffu, l_acc1, 2);
    if (l4 == 0) { s_lw[wn*64 + r0] = l_acc0; s_lw[wn*64 + r0 + 8] = l_acc1; }

    float* sO = smf;   // reuse K buffers: [64 rows][stride 130]
    if (wn == 1) {
        #pragma unroll
        for (int nt = 0; nt < 16; nt++) {
            const int col = 8*nt + 2*l4;
            *reinterpret_cast<float2*>(&sO[(r0    )*130 + col]) = make_float2(oacc[nt][0], oacc[nt][1]);
            *reinterpret_cast<float2*>(&sO[(r0 + 8)*130 + col]) = make_float2(oacc[nt][2], oacc[nt][3]);
        }
    }
    __syncthreads();
    if (wn == 0) {
        const float inv0 = 1.f / ((s_lw[r0]     + s_lw[64 + r0]    ) * 11.313708499f);
        const float inv1 = 1.f / ((s_lw[r0 + 8] + s_lw[64 + r0 + 8]) * 11.313708499f);
        #pragma unroll
        for (int nt = 0; nt < 16; nt++) {
            const int col = 8*nt + 2*l4;
            float2 p0 = *reinterpret_cast<const float2*>(&sO[(r0    )*130 + col]);
            float2 p1 = *reinterpret_cast<const float2*>(&sO[(r0 + 8)*130 + col]);
            *reinterpret_cast<float2*>(&g_attn[(size_t)(b*WHQ + q0 + r0)*CC + col]) =
                make_float2((oacc[nt][0] + p0.x)*inv0, (oacc[nt][1] + p0.y)*inv0);
            *reinterpret_cast<float2*>(&g_attn[(size_t)(b*WHQ + q0 + r0 + 8)*CC + col]) =
                make_float2((oacc[nt][2] + p1.x)*inv1, (oacc[nt][3] + p1.y)*inv1);
        }
    }
}

// ---------------------------------------------------------------------------
// K4: out = (attn @ Wo + bo) * (1+sigmoid(geo)) + feat0, transposed store
// ---------------------------------------------------------------------------
__global__ __launch_bounds__(256) void out_kernel(
    const float* __restrict__ Wo, const float* __restrict__ bo,
    const float* __restrict__ feat0, float* __restrict__ out)
{
    __shared__ float s_A[32][CC + 1];
    const int b  = blockIdx.y;
    const int q0 = blockIdx.x * 32;
    const int tid = threadIdx.x;
    const int tx = tid & 31;
    const int ty = tid >> 5;

    #pragma unroll
    for (int i = tid; i < 32*CC; i += 256) {
        int q = i >> 7, c = i & 127;
        s_A[q][c] = g_attn[(b*WHQ + q0 + q)*CC + c];
    }
    __syncthreads();

    float acc[16];
    #pragma unroll
    for (int j = 0; j < 16; j++) acc[j] = bo[ty*16 + j];

    #pragma unroll 4
    for (int c = 0; c < CC; c++) {
        const float a = s_A[tx][c];
        const float4* w4 = reinterpret_cast<const float4*>(&Wo[c*CC + ty*16]);
        #pragma unroll
        for (int j4 = 0; j4 < 4; j4++) {
            float4 w = w4[j4];
            acc[j4*4+0] = fmaf(a, w.x, acc[j4*4+0]);
            acc[j4*4+1] = fmaf(a, w.y, acc[j4*4+1]);
            acc[j4*4+2] = fmaf(a, w.z, acc[j4*4+2]);
            acc[j4*4+3] = fmaf(a, w.w, acc[j4*4+3]);
        }
    }

    #pragma unroll
    for (int j = 0; j < 16; j++) {
        const int cout = ty*16 + j;
        const float g = g_geo[(b*WHQ + q0 + tx)*CC + cout];
        const float sig = 1.f / (1.f + __expf(-g));
        const float v = acc[j]*(1.f + sig) + feat0[(b*CC + cout)*WHQ + q0 + tx];
        out[(b*CC + cout)*WHQ + q0 + tx] = v;
    }
}

// ---------------------------------------------------------------------------
extern "C" void kernel_launch(void* const* d_in, const int* in_sizes, int n_in,
                              void* d_out, int out_size)
{
    const float* feat0     = (const float*)d_in[0];
    const float* feat1     = (const float*)d_in[1];
    const float* geo_embed = (const float*)d_in[2];
    const float* Wq = (const float*)d_in[3];
    const float* bq = (const float*)d_in[4];
    const float* Wk = (const float*)d_in[5];
    const float* bk = (const float*)d_in[6];
    const float* Wv = (const float*)d_in[7];
    const float* bv = (const float*)d_in[8];
    const float* Wo = (const float*)d_in[9];
    const float* bo = (const float*)d_in[10];
    const float* Wg = (const float*)d_in[11];
    const float* bg = (const float*)d_in[12];
    const float* Wgate = (const float*)d_in[13];
    const float* bgate = (const float*)d_in[14];
    float* out = (float*)d_out;

    cudaFuncSetAttribute(attn_kernel,
                         cudaFuncAttributeMaxDynamicSharedMemorySize,
                         ATTN_SMEM_BYTES);

    kv_proj_kernel<<<dim3(NN/32, BB), 256>>>(feat1, Wk, bk, Wv, bv);
    q_geo_kernel<<<dim3(WHQ/32, BB), 256>>>(feat0, geo_embed, Wq, bq, Wg, bg, Wgate, bgate);
    attn_kernel<<<dim3(WHQ/TQ, BB), 256, ATTN_SMEM_BYTES>>>();
    out_kernel<<<dim3(WHQ/32, BB), 256>>>(Wo, bo, feat0, out);
}

// round 6
// speedup vs baseline: 3.6169x; 1.1866x over previous
#include <cuda_runtime.h>
#include <cuda_fp16.h>
#include <cuda_bf16.h>
#include <cstdint>

#define BB   8
#define CC   128
#define WHQ  2304
#define NN   8192

#define TQ   64
#define TN   64
#define NT   (NN/TN)
#define KSTRH 136    // K/Q tile stride (halves): 272B rows -> 4-bank shift, ldmatrix conflict-free
#define VSTRH 72     // V^T tile stride (halves): 144B rows -> 4-bank shift, conflict-free

// Scratch (device globals: allocation-free rule)
__device__ __half        g_pk  [BB*NN*CC];   // [b, n, c] fp16
__device__ __nv_bfloat16 g_pvT [BB*CC*NN];   // [b, c, n] bf16 (V transposed)
__device__ __half        g_pq  [BB*WHQ*CC];  // fp16
__device__ float         g_geo [BB*WHQ*CC];
__device__ float         g_attn[BB*WHQ*CC];

__device__ __forceinline__ void mma_f16(float c[4], const uint32_t a[4], uint32_t b0, uint32_t b1) {
    asm volatile(
        "mma.sync.aligned.m16n8k16.row.col.f32.f16.f16.f32 "
        "{%0,%1,%2,%3}, {%4,%5,%6,%7}, {%8,%9}, {%0,%1,%2,%3};"
        : "+f"(c[0]), "+f"(c[1]), "+f"(c[2]), "+f"(c[3])
        : "r"(a[0]), "r"(a[1]), "r"(a[2]), "r"(a[3]), "r"(b0), "r"(b1));
}

__device__ __forceinline__ void mma_bf16(float c[4], const uint32_t a[4], uint32_t b0, uint32_t b1) {
    asm volatile(
        "mma.sync.aligned.m16n8k16.row.col.f32.bf16.bf16.f32 "
        "{%0,%1,%2,%3}, {%4,%5,%6,%7}, {%8,%9}, {%0,%1,%2,%3};"
        : "+f"(c[0]), "+f"(c[1]), "+f"(c[2]), "+f"(c[3])
        : "r"(a[0]), "r"(a[1]), "r"(a[2]), "r"(a[3]), "r"(b0), "r"(b1));
}

// reg = {lo, hi}
__device__ __forceinline__ uint32_t pack_bf16(float hi, float lo) {
    uint32_t r;
    asm("cvt.rn.bf16x2.f32 %0, %1, %2;" : "=r"(r) : "f"(hi), "f"(lo));
    return r;
}

#define LDMX4(r0, r1, r2, r3, addr) \
    asm volatile("ldmatrix.sync.aligned.m8n8.x4.shared.b16 {%0,%1,%2,%3}, [%4];" \
        : "=r"(r0), "=r"(r1), "=r"(r2), "=r"(r3) : "r"(addr))

#define CP_ASYNC16(dst_u32, src_ptr) \
    asm volatile("cp.async.cg.shared.global [%0], [%1], 16;" :: "r"(dst_u32), "l"(src_ptr))
#define CP_COMMIT() asm volatile("cp.async.commit_group;")
#define CP_WAIT0()  asm volatile("cp.async.wait_group 0;" ::: "memory")

// ---------------------------------------------------------------------------
// K1: pk = feat1^T @ Wk + bk (fp16, [b,n,c]); pvT = (feat1^T @ Wv + bv)^T bf16
// ---------------------------------------------------------------------------
__global__ __launch_bounds__(256) void kv_proj_kernel(
    const float* __restrict__ feat1,
    const float* __restrict__ Wk, const float* __restrict__ bk,
    const float* __restrict__ Wv, const float* __restrict__ bv)
{
    __shared__ float s_in[32][CC + 1];
    const int b  = blockIdx.y;
    const int n0 = blockIdx.x * 32;
    const int tid = threadIdx.x;
    const int tx = tid & 31;
    const int ty = tid >> 5;

    #pragma unroll
    for (int c = ty; c < CC; c += 8)
        s_in[tx][c] = feat1[(b*CC + c)*NN + n0 + tx];
    __syncthreads();

    float accK[16], accV[16];
    #pragma unroll
    for (int j = 0; j < 16; j++) { accK[j] = bk[ty*16 + j]; accV[j] = bv[ty*16 + j]; }

    #pragma unroll 4
    for (int c = 0; c < CC; c++) {
        const float a = s_in[tx][c];
        const float4* wk4 = reinterpret_cast<const float4*>(&Wk[c*CC + ty*16]);
        const float4* wv4 = reinterpret_cast<const float4*>(&Wv[c*CC + ty*16]);
        #pragma unroll
        for (int j4 = 0; j4 < 4; j4++) {
            float4 k4 = wk4[j4];
            float4 v4 = wv4[j4];
            accK[j4*4+0] = fmaf(a, k4.x, accK[j4*4+0]);
            accK[j4*4+1] = fmaf(a, k4.y, accK[j4*4+1]);
            accK[j4*4+2] = fmaf(a, k4.z, accK[j4*4+2]);
            accK[j4*4+3] = fmaf(a, k4.w, accK[j4*4+3]);
            accV[j4*4+0] = fmaf(a, v4.x, accV[j4*4+0]);
            accV[j4*4+1] = fmaf(a, v4.y, accV[j4*4+1]);
            accV[j4*4+2] = fmaf(a, v4.z, accV[j4*4+2]);
            accV[j4*4+3] = fmaf(a, v4.w, accV[j4*4+3]);
        }
    }

    const size_t base = (size_t)(b*NN + n0 + tx)*CC + ty*16;
    #pragma unroll
    for (int j2 = 0; j2 < 8; j2++)
        *reinterpret_cast<__half2*>(&g_pk[base + j2*2]) =
            __floats2half2_rn(accK[j2*2], accK[j2*2+1]);
    #pragma unroll
    for (int j = 0; j < 16; j++)
        g_pvT[(size_t)(b*CC + ty*16 + j)*NN + n0 + tx] = __float2bfloat16(accV[j]);
}

// ---------------------------------------------------------------------------
// K2: pq (gated, fp16) + geo (exact fp32)
// ---------------------------------------------------------------------------
__global__ __launch_bounds__(256) void q_geo_kernel(
    const float* __restrict__ feat0, const float* __restrict__ geo_embed,
    const float* __restrict__ Wq, const float* __restrict__ bq,
    const float* __restrict__ Wg, const float* __restrict__ bg,
    const float* __restrict__ Wgate, const float* __restrict__ bgate)
{
    __shared__ float s_q[32][CC + 1];
    __shared__ float s_g[32][CC + 1];
    __shared__ float s_part[8][32];
    __shared__ float s_gate[32];

    const int b  = blockIdx.y;
    const int q0 = blockIdx.x * 32;
    const int tid = threadIdx.x;
    const int tx = tid & 31;
    const int ty = tid >> 5;

    #pragma unroll
    for (int c = ty; c < CC; c += 8)
        s_q[tx][c] = feat0[(b*CC + c)*WHQ + q0 + tx];
    #pragma unroll
    for (int i = tid; i < 32*CC; i += 256) {
        int q = i >> 7, c = i & 127;
        s_g[q][c] = geo_embed[(b*WHQ + q0 + q)*CC + c];
    }
    __syncthreads();

    float aq[16], ag[16];
    #pragma unroll
    for (int j = 0; j < 16; j++) { aq[j] = bq[ty*16 + j]; ag[j] = bg[ty*16 + j]; }

    #pragma unroll 4
    for (int c = 0; c < CC; c++) {
        const float xq = s_q[tx][c];
        const float xg = s_g[tx][c];
        const float4* wq4 = reinterpret_cast<const float4*>(&Wq[c*CC + ty*16]);
        const float4* wg4 = reinterpret_cast<const float4*>(&Wg[c*CC + ty*16]);
        #pragma unroll
        for (int j4 = 0; j4 < 4; j4++) {
            float4 q4 = wq4[j4];
            float4 g4 = wg4[j4];
            aq[j4*4+0] = fmaf(xq, q4.x, aq[j4*4+0]);
            aq[j4*4+1] = fmaf(xq, q4.y, aq[j4*4+1]);
            aq[j4*4+2] = fmaf(xq, q4.z, aq[j4*4+2]);
            aq[j4*4+3] = fmaf(xq, q4.w, aq[j4*4+3]);
            ag[j4*4+0] = fmaf(xg, g4.x, ag[j4*4+0]);
            ag[j4*4+1] = fmaf(xg, g4.y, ag[j4*4+1]);
            ag[j4*4+2] = fmaf(xg, g4.z, ag[j4*4+2]);
            ag[j4*4+3] = fmaf(xg, g4.w, ag[j4*4+3]);
        }
    }

    float part = 0.f;
    #pragma unroll
    for (int j = 0; j < 16; j++)
        part += aq[j]*Wgate[ty*16 + j] + ag[j]*Wgate[CC + ty*16 + j];
    s_part[ty][tx] = part;
    __syncthreads();
    if (ty == 0) {
        float s = bgate[0];
        #pragma unroll
        for (int k = 0; k < 8; k++) s += s_part[k][tx];
        s_gate[tx] = 1.f / (1.f + __expf(-s));
    }
    __syncthreads();
    const float gate = s_gate[tx];

    const size_t base = (size_t)(b*WHQ + q0 + tx)*CC + ty*16;
    #pragma unroll
    for (int j2 = 0; j2 < 8; j2++)
        *reinterpret_cast<__half2*>(&g_pq[base + j2*2]) =
            __floats2half2_rn(aq[j2*2]   + gate*ag[j2*2],
                              aq[j2*2+1] + gate*ag[j2*2+1]);
    #pragma unroll
    for (int j4 = 0; j4 < 4; j4++)
        *reinterpret_cast<float4*>(&g_geo[base + j4*4]) =
            make_float4(ag[j4*4+0], ag[j4*4+1], ag[j4*4+2], ag[j4*4+3]);
}

// ---------------------------------------------------------------------------
// K3: flash attention. QK fp16 m16n8k16 (ldmatrix Q/K), PV bf16 m16n8k16
//     (P regs, ldmatrix V). Fixed per-row m0 from tile 0, l in regs.
//     8 warps: wm rows 16wm..+15, wn = S-col half / PV split-K half.
// ---------------------------------------------------------------------------
#define SM_K0B 0
#define SM_K1B (TQ*KSTRH*2)                 // 17408
#define SM_V0B (2*TQ*KSTRH*2)               // 34816
#define SM_V1B (SM_V0B + CC*VSTRH*2)        // +18432
#define SM_MXB (SM_V0B + 2*CC*VSTRH*2)      // 71680: 128 floats
#define SM_LWB (SM_MXB + 512)               // 128 floats
#define ATTN_SMEM_BYTES (SM_LWB + 512)

__global__ void __launch_bounds__(256, 1) attn_kernel()
{
    extern __shared__ __align__(128) char smc[];
    float* smf = reinterpret_cast<float*>(smc);
    const uint32_t smem_u32 = (uint32_t)__cvta_generic_to_shared(smc);

    const int b   = blockIdx.y;
    const int q0  = blockIdx.x * TQ;
    const int tid = threadIdx.x;
    const int lane = tid & 31;
    const int wid  = tid >> 5;
    const int wm   = wid & 3;
    const int wn   = wid >> 2;
    const int l4   = lane & 3;
    const int ld   = lane >> 2;
    const int r0   = 16*wm + ld;

    float* s_mx = smf + SM_MXB/4;   // [2][64]
    float* s_lw = smf + SM_LWB/4;   // [2][64]

    const __half* gq = g_pq + (size_t)(b*WHQ + q0)*CC;
    const __half* gk = g_pk + (size_t)b*NN*CC;
    const __nv_bfloat16* gvT = g_pvT + (size_t)b*CC*NN;

    // per-lane ldmatrix base offsets (bytes)
    const int li = lane & 7, lg = lane >> 3;
    const uint32_t q_off = (uint32_t)((16*wm + (lg&1)*8 + li)*(KSTRH*2) + (lg>>1)*16);
    const uint32_t k_off = (uint32_t)((32*wn + (lg>>1)*8 + li)*(KSTRH*2) + (lg&1)*16);
    const uint32_t v_off = (uint32_t)(((lg>>1)*8 + li)*(VSTRH*2) + 64*wn + (lg&1)*16);

    // ---- stage Q into K-buf0 (cp.async), extract A-fragments ----
    {
        #pragma unroll
        for (int j = 0; j < 4; j++) {
            int idx = j*256 + tid;
            int n = idx >> 4, ck = idx & 15;
            CP_ASYNC16(smem_u32 + SM_K0B + (uint32_t)(n*(KSTRH*2) + ck*16),
                       gq + (size_t)n*CC + ck*8);
        }
        CP_COMMIT();
        CP_WAIT0();
    }
    __syncthreads();
    uint32_t qa[8][4];
    #pragma unroll
    for (int kc = 0; kc < 8; kc++)
        LDMX4(qa[kc][0], qa[kc][1], qa[kc][2], qa[kc][3],
              smem_u32 + SM_K0B + q_off + kc*32);
    __syncthreads();   // Q fully read before K tile 0 overwrites buf0

    // ---- tile loader (K fp16 16KB, V^T bf16 16KB) ----
    auto load_tile = [&](int t, int buf) {
        const uint32_t kb = smem_u32 + (buf ? SM_K1B : SM_K0B);
        const uint32_t vb = smem_u32 + (buf ? SM_V1B : SM_V0B);
        const __half* ksrc = gk + (size_t)t*TN*CC;
        #pragma unroll
        for (int j = 0; j < 4; j++) {
            int idx = j*256 + tid;
            int n = idx >> 4, ck = idx & 15;
            CP_ASYNC16(kb + (uint32_t)(n*(KSTRH*2) + ck*16), ksrc + (size_t)n*CC + ck*8);
        }
        #pragma unroll
        for (int j = 0; j < 4; j++) {
            int idx = j*256 + tid;
            int c = idx >> 3, ck = idx & 7;
            CP_ASYNC16(vb + (uint32_t)(c*(VSTRH*2) + ck*16),
                       gvT + (size_t)c*NN + (size_t)t*TN + ck*8);
        }
        CP_COMMIT();
    };

    load_tile(0, 0);

    float oacc[16][4];
    #pragma unroll
    for (int i = 0; i < 16; i++)
        #pragma unroll
        for (int j = 0; j < 4; j++) oacc[i][j] = 0.f;
    float l_acc0 = 0.f, l_acc1 = 0.f;
    float m0a = 0.f, m0b = 0.f;

    for (int t = 0; t < NT; ++t) {
        CP_WAIT0();
        __syncthreads();
        if (t + 1 < NT) load_tile(t+1, (t+1)&1);

        const uint32_t kb = smem_u32 + ((t & 1) ? SM_K1B : SM_K0B);
        const uint32_t vb = smem_u32 + ((t & 1) ? SM_V1B : SM_V0B);

        // ---- S = Q @ K^T (fp16 tensor cores) ----
        float sacc[4][4];
        #pragma unroll
        for (int nt = 0; nt < 4; nt++)
            #pragma unroll
            for (int j = 0; j < 4; j++) sacc[nt][j] = 0.f;

        #pragma unroll
        for (int kc = 0; kc < 8; kc++) {
            uint32_t b0, b1, b2, b3, b4, b5, b6, b7;
            LDMX4(b0, b1, b2, b3, kb + k_off + kc*32);          // nt 0,1
            LDMX4(b4, b5, b6, b7, kb + k_off + 4352 + kc*32);   // nt 2,3 (16 rows * 272B)
            mma_f16(sacc[0], qa[kc], b0, b1);
            mma_f16(sacc[1], qa[kc], b2, b3);
            mma_f16(sacc[2], qa[kc], b4, b5);
            mma_f16(sacc[3], qa[kc], b6, b7);
        }

        // ---- per-row m0 from tile 0 only ----
        if (t == 0) {
            float mx0 = -1e30f, mx1 = -1e30f;
            #pragma unroll
            for (int nt = 0; nt < 4; nt++) {
                mx0 = fmaxf(mx0, fmaxf(sacc[nt][0], sacc[nt][1]));
                mx1 = fmaxf(mx1, fmaxf(sacc[nt][2], sacc[nt][3]));
            }
            mx0 = fmaxf(mx0, __shfl_xor_sync(0xffffffffu, mx0, 1));
            mx0 = fmaxf(mx0, __shfl_xor_sync(0xffffffffu, mx0, 2));
            mx1 = fmaxf(mx1, __shfl_xor_sync(0xffffffffu, mx1, 1));
            mx1 = fmaxf(mx1, __shfl_xor_sync(0xffffffffu, mx1, 2));
            if (l4 == 0) { s_mx[wn*64 + r0] = mx0; s_mx[wn*64 + r0 + 8] = mx1; }
            __syncthreads();
            m0a = fmaxf(s_mx[r0],     s_mx[64 + r0]);
            m0b = fmaxf(s_mx[r0 + 8], s_mx[64 + r0 + 8]);
        }

        // ---- exp + pack P (bf16 regs), accumulate l ----
        uint32_t pa[2][4];
        float ls0 = 0.f, ls1 = 0.f;
        #pragma unroll
        for (int nt = 0; nt < 4; nt++) {
            float p0 = __expf(sacc[nt][0] - m0a);
            float p1 = __expf(sacc[nt][1] - m0a);
            float p2 = __expf(sacc[nt][2] - m0b);
            float p3 = __expf(sacc[nt][3] - m0b);
            ls0 += p0 + p1;
            ls1 += p2 + p3;
            const int kc = nt >> 1, o = (nt & 1) ? 2 : 0;
            pa[kc][o + 0] = pack_bf16(p1, p0);
            pa[kc][o + 1] = pack_bf16(p3, p2);
        }
        l_acc0 += ls0;
        l_acc1 += ls1;

        // ---- O += P @ V (bf16 tensor cores, split-K over wn) ----
        #pragma unroll
        for (int kc = 0; kc < 2; kc++) {
            #pragma unroll
            for (int j = 0; j < 8; j++) {
                uint32_t v0, v1, v2, v3;
                LDMX4(v0, v1, v2, v3, vb + v_off + j*2304 + kc*32);  // 16 rows * 144B
                mma_bf16(oacc[2*j],   pa[kc], v0, v1);
                mma_bf16(oacc[2*j+1], pa[kc], v2, v3);
            }
        }
    }

    // ---- epilogue: reduce l, merge wn partials, scale, store ----
    l_acc0 += __shfl_xor_sync(0xffffffffu, l_acc0, 1);
    l_acc0 += __shfl_xor_sync(0xffffffffu, l_acc0, 2);
    l_acc1 += __shfl_xor_sync(0xffffffffu, l_acc1, 1);
    l_acc1 += __shfl_xor_sync(0xffffffffu, l_acc1, 2);
    if (l4 == 0) { s_lw[wn*64 + r0] = l_acc0; s_lw[wn*64 + r0 + 8] = l_acc1; }

    float* sO = smf;   // reuse K/V buffers: [64 rows][stride 130] = 33280B < 34816B
    if (wn == 1) {
        #pragma unroll
        for (int nt = 0; nt < 16; nt++) {
            const int col = 8*nt + 2*l4;
            *reinterpret_cast<float2*>(&sO[(r0    )*130 + col]) = make_float2(oacc[nt][0], oacc[nt][1]);
            *reinterpret_cast<float2*>(&sO[(r0 + 8)*130 + col]) = make_float2(oacc[nt][2], oacc[nt][3]);
        }
    }
    __syncthreads();
    if (wn == 0) {
        const float inv0 = 1.f / ((s_lw[r0]     + s_lw[64 + r0]    ) * 11.313708499f);
        const float inv1 = 1.f / ((s_lw[r0 + 8] + s_lw[64 + r0 + 8]) * 11.313708499f);
        #pragma unroll
        for (int nt = 0; nt < 16; nt++) {
            const int col = 8*nt + 2*l4;
            float2 p0 = *reinterpret_cast<const float2*>(&sO[(r0    )*130 + col]);
            float2 p1 = *reinterpret_cast<const float2*>(&sO[(r0 + 8)*130 + col]);
            *reinterpret_cast<float2*>(&g_attn[(size_t)(b*WHQ + q0 + r0)*CC + col]) =
                make_float2((oacc[nt][0] + p0.x)*inv0, (oacc[nt][1] + p0.y)*inv0);
            *reinterpret_cast<float2*>(&g_attn[(size_t)(b*WHQ + q0 + r0 + 8)*CC + col]) =
                make_float2((oacc[nt][2] + p1.x)*inv1, (oacc[nt][3] + p1.y)*inv1);
        }
    }
}

// ---------------------------------------------------------------------------
// K4: out = (attn @ Wo + bo) * (1+sigmoid(geo)) + feat0, transposed store
// ---------------------------------------------------------------------------
__global__ __launch_bounds__(256) void out_kernel(
    const float* __restrict__ Wo, const float* __restrict__ bo,
    const float* __restrict__ feat0, float* __restrict__ out)
{
    __shared__ float s_A[32][CC + 1];
    const int b  = blockIdx.y;
    const int q0 = blockIdx.x * 32;
    const int tid = threadIdx.x;
    const int tx = tid & 31;
    const int ty = tid >> 5;

    #pragma unroll
    for (int i = tid; i < 32*CC; i += 256) {
        int q = i >> 7, c = i & 127;
        s_A[q][c] = g_attn[(b*WHQ + q0 + q)*CC + c];
    }
    __syncthreads();

    float acc[16];
    #pragma unroll
    for (int j = 0; j < 16; j++) acc[j] = bo[ty*16 + j];

    #pragma unroll 4
    for (int c = 0; c < CC; c++) {
        const float a = s_A[tx][c];
        const float4* w4 = reinterpret_cast<const float4*>(&Wo[c*CC + ty*16]);
        #pragma unroll
        for (int j4 = 0; j4 < 4; j4++) {
            float4 w = w4[j4];
            acc[j4*4+0] = fmaf(a, w.x, acc[j4*4+0]);
            acc[j4*4+1] = fmaf(a, w.y, acc[j4*4+1]);
            acc[j4*4+2] = fmaf(a, w.z, acc[j4*4+2]);
            acc[j4*4+3] = fmaf(a, w.w, acc[j4*4+3]);
        }
    }

    #pragma unroll
    for (int j = 0; j < 16; j++) {
        const int cout = ty*16 + j;
        const float g = g_geo[(b*WHQ + q0 + tx)*CC + cout];
        const float sig = 1.f / (1.f + __expf(-g));
        const float v = acc[j]*(1.f + sig) + feat0[(b*CC + cout)*WHQ + q0 + tx];
        out[(b*CC + cout)*WHQ + q0 + tx] = v;
    }
}

// ---------------------------------------------------------------------------
extern "C" void kernel_launch(void* const* d_in, const int* in_sizes, int n_in,
                              void* d_out, int out_size)
{
    const float* feat0     = (const float*)d_in[0];
    const float* feat1     = (const float*)d_in[1];
    const float* geo_embed = (const float*)d_in[2];
    const float* Wq = (const float*)d_in[3];
    const float* bq = (const float*)d_in[4];
    const float* Wk = (const float*)d_in[5];
    const float* bk = (const float*)d_in[6];
    const float* Wv = (const float*)d_in[7];
    const float* bv = (const float*)d_in[8];
    const float* Wo = (const float*)d_in[9];
    const float* bo = (const float*)d_in[10];
    const float* Wg = (const float*)d_in[11];
    const float* bg = (const float*)d_in[12];
    const float* Wgate = (const float*)d_in[13];
    const float* bgate = (const float*)d_in[14];
    float* out = (float*)d_out;

    cudaFuncSetAttribute(attn_kernel,
                         cudaFuncAttributeMaxDynamicSharedMemorySize,
                         ATTN_SMEM_BYTES);

    kv_proj_kernel<<<dim3(NN/32, BB), 256>>>(feat1, Wk, bk, Wv, bv);
    q_geo_kernel<<<dim3(WHQ/32, BB), 256>>>(feat0, geo_embed, Wq, bq, Wg, bg, Wgate, bgate);
    attn_kernel<<<dim3(WHQ/TQ, BB), 256, ATTN_SMEM_BYTES>>>();
    out_kernel<<<dim3(WHQ/32, BB), 256>>>(Wo, bo, feat0, out);
}